// round 1
// baseline (speedup 1.0000x reference)
#include <cuda_runtime.h>
#include <cuda_bf16.h>
#include <math_constants.h>

// ----------------------------------------------------------------------------
// LSTMSpatial: B=2048, E=H=D=512, K=64
// Inputs (metadata order):
//  0 inputs  [2048,512]  1 hx [2048,512]  2 cx [2048,512]
//  3 features[2048,512,64]
//  4 W_ih [2048,512]  5 W_hh [2048,512]  6 b_ih [2048]  7 b_hh [2048]
//  8 W_ht [512,512]   9 b_ht [512]      10 attn_w [512] 11 attn_b [1]
// Output: hy [2048,512] then cy [2048,512] concatenated.
// ----------------------------------------------------------------------------

#define Bdim 2048
#define Hdim 512
#define Ddim 512
#define Kdim 64

// Scratch (device globals: allocation-free rule)
__device__ float g_gates[Bdim * 4 * Hdim];   // 16 MB
__device__ float g_wh[Bdim * Hdim];          //  4 MB

__device__ __forceinline__ float tanhapx(float x) {
    float y;
    asm("tanh.approx.f32 %0, %1;" : "=f"(y) : "f"(x));
    return y;
}
__device__ __forceinline__ float sigm(float x) {
    return fmaf(0.5f, tanhapx(0.5f * x), 0.5f);
}

// ----------------------------------------------------------------------------
// GEMM: C[M,N] = A[M,K]*W[N,K]^T (+ optional second K-source) + bias
// A,W row-major with K contiguous, leading dim 512 per source.
// BM=BN=128, BK=16, 256 threads, 8x8 per thread.
// which==0 -> C=g_gates (N=2048), which==1 -> C=g_wh (N=512)
// ----------------------------------------------------------------------------
__global__ __launch_bounds__(256) void gemm_kernel(
    const float* __restrict__ A0, const float* __restrict__ A1,
    const float* __restrict__ W0, const float* __restrict__ W1,
    const float* __restrict__ bias0, const float* __restrict__ bias1,
    int nkt, int which)
{
    __shared__ float As[16][132];
    __shared__ float Bs[16][132];

    const int tid = threadIdx.x;
    const int m0 = blockIdx.y * 128;
    const int n0 = blockIdx.x * 128;
    const int tx = tid & 15;   // n direction
    const int ty = tid >> 4;   // m direction

    float acc[8][8];
    #pragma unroll
    for (int i = 0; i < 8; i++)
        #pragma unroll
        for (int j = 0; j < 8; j++) acc[i][j] = 0.f;

    for (int kt = 0; kt < nkt; ++kt) {
        const float* A = (kt < 32) ? A0 : A1;
        const float* W = (kt < 32) ? W0 : W1;
        const int k0 = (kt & 31) * 16;

        #pragma unroll
        for (int i = 0; i < 2; ++i) {
            int idx = tid + i * 256;       // 0..511
            int row = idx >> 2;            // 0..127
            int c4  = idx & 3;             // 0..3
            float4 va = *(const float4*)(A + (size_t)(m0 + row) * 512 + k0 + c4 * 4);
            As[c4 * 4 + 0][row] = va.x; As[c4 * 4 + 1][row] = va.y;
            As[c4 * 4 + 2][row] = va.z; As[c4 * 4 + 3][row] = va.w;
            float4 vb = *(const float4*)(W + (size_t)(n0 + row) * 512 + k0 + c4 * 4);
            Bs[c4 * 4 + 0][row] = vb.x; Bs[c4 * 4 + 1][row] = vb.y;
            Bs[c4 * 4 + 2][row] = vb.z; Bs[c4 * 4 + 3][row] = vb.w;
        }
        __syncthreads();

        #pragma unroll
        for (int kk = 0; kk < 16; ++kk) {
            float a[8], b[8];
            #pragma unroll
            for (int i = 0; i < 8; i++) a[i] = As[kk][ty * 8 + i];
            #pragma unroll
            for (int i = 0; i < 8; i++) b[i] = Bs[kk][tx * 8 + i];
            #pragma unroll
            for (int i = 0; i < 8; i++)
                #pragma unroll
                for (int j = 0; j < 8; j++)
                    acc[i][j] = fmaf(a[i], b[j], acc[i][j]);
        }
        __syncthreads();
    }

    float* C = (which == 0) ? g_gates : g_wh;
    const int N = (which == 0) ? 2048 : 512;

    #pragma unroll
    for (int i = 0; i < 8; i++) {
        int m = m0 + ty * 8 + i;
        #pragma unroll
        for (int j = 0; j < 8; j++) {
            int n = n0 + tx * 8 + j;
            float bsum = bias0 ? bias0[n] : 0.f;
            if (bias1) bsum += bias1[n];
            C[(size_t)m * N + n] = acc[i][j] + bsum;
        }
    }
}

// ----------------------------------------------------------------------------
// LSTM elementwise: gates (i,f,g,o) -> hy.  (c_new is not an output.)
// ----------------------------------------------------------------------------
__global__ __launch_bounds__(256) void lstm_elem_kernel(
    const float* __restrict__ cx, float* __restrict__ hy)
{
    int idx = blockIdx.x * blockDim.x + threadIdx.x;  // b*512 + h
    int b = idx >> 9, h = idx & 511;
    const float* g = g_gates + (size_t)b * 2048;
    float gi = g[h];
    float gf = g[512 + h];
    float gg = g[1024 + h];
    float go = g[1536 + h];
    float cn = sigm(gf) * cx[idx] + sigm(gi) * tanhapx(gg);
    hy[idx] = sigm(go) * tanhapx(cn);
}

// ----------------------------------------------------------------------------
// Fused attention: per batch row b (one CTA, 512 threads).
// Streams features[b] (128 KB) from GMEM once: computes z on the fly while
// staging into pad-65 SMEM; softmax over K=64 (attn_b cancels); cy from SMEM.
// ----------------------------------------------------------------------------
__global__ __launch_bounds__(512) void attn_kernel(
    const float* __restrict__ features,
    const float* __restrict__ attn_w,
    float* __restrict__ cy)
{
    extern __shared__ float sm[];
    float* SF  = sm;               // 512*65
    float* WhS = SF + 512 * 65;    // 512
    float* AW  = WhS + 512;        // 512
    float* ZP  = AW + 512;         // 512 (8 x 64 partials)
    float* WK  = ZP + 512;         // 64 softmax weights
    float* RED = WK + 64;          // 4

    const int b = blockIdx.x;
    const int tid = threadIdx.x;

    WhS[tid] = g_wh[(size_t)b * 512 + tid];
    AW[tid]  = attn_w[tid];
    __syncthreads();

    const int k = tid & 63;
    const int j = tid >> 6;   // 0..7: d-chunk
    const float* fb = features + (size_t)b * (512 * 64);

    // Phase 1: stream + stage + partial z
    float zacc = 0.f;
    #pragma unroll 8
    for (int dd = 0; dd < 64; ++dd) {
        int d = j * 64 + dd;
        float v = fb[d * 64 + k];
        SF[d * 65 + k] = v;
        zacc = fmaf(tanhapx(v + WhS[d]), AW[d], zacc);
    }
    ZP[j * 64 + k] = zacc;
    __syncthreads();

    // Phase 2: reduce partials, softmax over K=64 (threads 0..63 own z_k)
    float z = 0.f;
    if (tid < 64) {
        #pragma unroll
        for (int jj = 0; jj < 8; jj++) z += ZP[jj * 64 + tid];
    }
    float mv = (tid < 64) ? z : -CUDART_INF_F;
    #pragma unroll
    for (int off = 16; off; off >>= 1)
        mv = fmaxf(mv, __shfl_xor_sync(0xffffffffu, mv, off));
    if (tid < 64 && (tid & 31) == 0) RED[tid >> 5] = mv;
    __syncthreads();
    float mx = fmaxf(RED[0], RED[1]);
    float e = (tid < 64) ? __expf(z - mx) : 0.f;
    float sv = e;
    #pragma unroll
    for (int off = 16; off; off >>= 1)
        sv += __shfl_xor_sync(0xffffffffu, sv, off);
    if (tid < 64 && (tid & 31) == 0) RED[2 + (tid >> 5)] = sv;
    __syncthreads();
    float inv = 1.f / (RED[2] + RED[3]);
    if (tid < 64) WK[tid] = e * inv;
    __syncthreads();

    // Phase 3: cy[b,d] = sum_k SF[d,k] * w[k]  (pad-65 -> conflict-free)
    float acc = 0.f;
    const int d = tid;
    #pragma unroll
    for (int kk = 0; kk < 64; ++kk)
        acc = fmaf(SF[d * 65 + kk], WK[kk], acc);
    cy[(size_t)b * 512 + d] = acc;
}

// ----------------------------------------------------------------------------
extern "C" void kernel_launch(void* const* d_in, const int* in_sizes, int n_in,
                              void* d_out, int out_size)
{
    const float* x      = (const float*)d_in[0];
    const float* hx     = (const float*)d_in[1];
    const float* cx     = (const float*)d_in[2];
    const float* feats  = (const float*)d_in[3];
    const float* W_ih   = (const float*)d_in[4];
    const float* W_hh   = (const float*)d_in[5];
    const float* b_ih   = (const float*)d_in[6];
    const float* b_hh   = (const float*)d_in[7];
    const float* W_ht   = (const float*)d_in[8];
    const float* b_ht   = (const float*)d_in[9];
    const float* attn_w = (const float*)d_in[10];
    // attn_b (d_in[11]) cancels in softmax -> unused.

    float* hy = (float*)d_out;                      // [2048,512]
    float* cy = (float*)d_out + Bdim * Hdim;        // [2048,512]

    const int attn_smem = (512 * 65 + 512 + 512 + 512 + 64 + 4) * (int)sizeof(float);
    cudaFuncSetAttribute(attn_kernel, cudaFuncAttributeMaxDynamicSharedMemorySize, attn_smem);

    // 1) gates = [x|hx] @ [W_ih|W_hh]^T + b_ih + b_hh   (K = 1024 -> 64 k-tiles)
    gemm_kernel<<<dim3(16, 16), 256>>>(x, hx, W_ih, W_hh, b_ih, b_hh, 64, 0);

    // 2) LSTM elementwise -> hy
    lstm_elem_kernel<<<(Bdim * Hdim) / 256, 256>>>(cx, hy);

    // 3) Wh = hy @ W_ht^T + b_ht   (K = 512 -> 32 k-tiles)
    gemm_kernel<<<dim3(4, 16), 256>>>(hy, hy, W_ht, W_ht, b_ht, nullptr, 32, 1);

    // 4) fused attention -> cy
    attn_kernel<<<Bdim, 512, attn_smem>>>(feats, attn_w, cy);
}

// round 4
// speedup vs baseline: 1.9420x; 1.9420x over previous
#include <cuda_runtime.h>
#include <cuda_bf16.h>
#include <math_constants.h>
#include <stdint.h>

// ----------------------------------------------------------------------------
// LSTMSpatial: B=2048, E=H=D=512, K=64
// ----------------------------------------------------------------------------

#define Bdim 2048
#define Hdim 512

// Scratch (device globals: allocation-free rule)
__device__ float g_gates[Bdim * 4 * Hdim];   // 16 MB
__device__ float g_wh[Bdim * Hdim];          //  4 MB

__device__ __forceinline__ float tanhapx(float x) {
    float y;
    asm("tanh.approx.f32 %0, %1;" : "=f"(y) : "f"(x));
    return y;
}
__device__ __forceinline__ float sigm(float x) {
    return fmaf(0.5f, tanhapx(0.5f * x), 0.5f);
}

// ----------------------------------------------------------------------------
// Tensor-core GEMM: C[M,N] = A[M,K]*W[N,K]^T + bias  (fp32 in/out, bf16 split)
// A = Ah + Al (bf16), W = Wh + Wl (bf16): C ~= Ah*Wh + Ah*Wl + Al*Wh
// BM=128, BN=64, BK=16(fp32). 256 threads = 8 warps (4m x 2n), warp tile 32x32.
// Dual K-source: kt<32 uses A0/W0, else A1/W1 (each source ldK=512).
// ----------------------------------------------------------------------------
#define LDT 24   // bf16 elements per smem row (16 data + 8 pad = 48 bytes)

#define MMA_BF16(acc, af, bf)                                                 \
    asm volatile("mma.sync.aligned.m16n8k16.row.col.f32.bf16.bf16.f32 "       \
                 "{%0,%1,%2,%3}, {%4,%5,%6,%7}, {%8,%9}, {%0,%1,%2,%3};"      \
                 : "+f"(acc[0]), "+f"(acc[1]), "+f"(acc[2]), "+f"(acc[3])     \
                 : "r"(af[0]), "r"(af[1]), "r"(af[2]), "r"(af[3]),            \
                   "r"(bf[0]), "r"(bf[1]))

#define LDSM4(r, addr)                                                        \
    asm volatile("ldmatrix.sync.aligned.m8n8.x4.shared.b16 {%0,%1,%2,%3}, [%4];" \
                 : "=r"(r[0]), "=r"(r[1]), "=r"(r[2]), "=r"(r[3]) : "r"(addr))

// Split a float4 into hi/lo bf16x2 pairs and store (two 4B stores per tier).
__device__ __forceinline__ void split_store4(
    __nv_bfloat16* __restrict__ Hi, __nv_bfloat16* __restrict__ Lo,
    int off, float4 v)
{
    float2 p0 = {v.x, v.y}, p1 = {v.z, v.w};
    __nv_bfloat162 h0 = __float22bfloat162_rn(p0);
    __nv_bfloat162 h1 = __float22bfloat162_rn(p1);
    float2 r0 = {p0.x - __bfloat162float(h0.x), p0.y - __bfloat162float(h0.y)};
    float2 r1 = {p1.x - __bfloat162float(h1.x), p1.y - __bfloat162float(h1.y)};
    __nv_bfloat162 l0 = __float22bfloat162_rn(r0);
    __nv_bfloat162 l1 = __float22bfloat162_rn(r1);
    *(__nv_bfloat162*)(Hi + off)     = h0;
    *(__nv_bfloat162*)(Hi + off + 2) = h1;
    *(__nv_bfloat162*)(Lo + off)     = l0;
    *(__nv_bfloat162*)(Lo + off + 2) = l1;
}

__global__ __launch_bounds__(256) void gemm_tc_kernel(
    const float* __restrict__ A0, const float* __restrict__ A1,
    const float* __restrict__ W0, const float* __restrict__ W1,
    const float* __restrict__ bias0, const float* __restrict__ bias1,
    float* __restrict__ C, int N, int nkt)
{
    __shared__ __nv_bfloat16 Ah[128 * LDT], Al[128 * LDT];
    __shared__ __nv_bfloat16 Bh[64 * LDT],  Bl[64 * LDT];

    const int tid = threadIdx.x;
    const int wid = tid >> 5, lane = tid & 31;
    const int m0 = blockIdx.y * 128, n0 = blockIdx.x * 64;
    const int wm = (wid & 3) * 32;     // warp m base (2 m16 tiles)
    const int wn = (wid >> 2) * 32;    // warp n base (4 n8 tiles)

    // ldmatrix lane addressing (element offsets within tile)
    const int rowA = lane & 15, chA = lane >> 4;
    const int aoff = (wm + rowA) * LDT + chA * 8;
    const int q = lane >> 3, rB = lane & 7;
    const int rowB = rB + ((q >> 1) << 3), chB = q & 1;
    const int boff = (wn + rowB) * LDT + chB * 8;

    const uint32_t ah_s = (uint32_t)__cvta_generic_to_shared(Ah);
    const uint32_t al_s = (uint32_t)__cvta_generic_to_shared(Al);
    const uint32_t bh_s = (uint32_t)__cvta_generic_to_shared(Bh);
    const uint32_t bl_s = (uint32_t)__cvta_generic_to_shared(Bl);

    float acc[2][4][4];
    #pragma unroll
    for (int i = 0; i < 2; i++)
        #pragma unroll
        for (int j = 0; j < 4; j++)
            #pragma unroll
            for (int r = 0; r < 4; r++) acc[i][j][r] = 0.f;

    for (int kt = 0; kt < nkt; ++kt) {
        const float* A = (kt < 32) ? A0 : A1;
        const float* W = (kt < 32) ? W0 : W1;
        const int k0 = (kt & 31) * 16;

        // ---- stage A tile: 128x16 f32 -> hi/lo bf16 ----
        #pragma unroll
        for (int i = 0; i < 2; ++i) {
            int idx = tid + i * 256;           // 0..511
            int row = idx >> 2, c4 = idx & 3;
            float4 v = *(const float4*)(A + (size_t)(m0 + row) * 512 + k0 + c4 * 4);
            split_store4(Ah, Al, row * LDT + c4 * 4, v);
        }
        // ---- stage B tile: 64x16 f32 ----
        {
            int row = tid >> 2, c4 = tid & 3;  // 64 rows x 4 chunks = 256
            float4 v = *(const float4*)(W + (size_t)(n0 + row) * 512 + k0 + c4 * 4);
            split_store4(Bh, Bl, row * LDT + c4 * 4, v);
        }
        __syncthreads();

        // ---- fragments ----
        uint32_t ahf[2][4], alf[2][4], bhf[4][2], blf[4][2];
        #pragma unroll
        for (int tm = 0; tm < 2; ++tm) {
            uint32_t ad = ah_s + (uint32_t)(aoff + tm * 16 * LDT) * 2;
            LDSM4(ahf[tm], ad);
            uint32_t ad2 = al_s + (uint32_t)(aoff + tm * 16 * LDT) * 2;
            LDSM4(alf[tm], ad2);
        }
        #pragma unroll
        for (int p = 0; p < 2; ++p) {
            uint32_t r4[4];
            uint32_t bd = bh_s + (uint32_t)(boff + p * 16 * LDT) * 2;
            LDSM4(r4, bd);
            bhf[2*p][0] = r4[0]; bhf[2*p][1] = r4[1];
            bhf[2*p+1][0] = r4[2]; bhf[2*p+1][1] = r4[3];
            uint32_t bd2 = bl_s + (uint32_t)(boff + p * 16 * LDT) * 2;
            LDSM4(r4, bd2);
            blf[2*p][0] = r4[0]; blf[2*p][1] = r4[1];
            blf[2*p+1][0] = r4[2]; blf[2*p+1][1] = r4[3];
        }

        // ---- mma: hi*hi + hi*lo + lo*hi ----
        #pragma unroll
        for (int tm = 0; tm < 2; ++tm)
            #pragma unroll
            for (int tn = 0; tn < 4; ++tn) {
                MMA_BF16(acc[tm][tn], ahf[tm], bhf[tn]);
                MMA_BF16(acc[tm][tn], ahf[tm], blf[tn]);
                MMA_BF16(acc[tm][tn], alf[tm], bhf[tn]);
            }
        __syncthreads();
    }

    // ---- epilogue: bias + store ----
    const int gid = lane >> 2, tig = lane & 3;
    #pragma unroll
    for (int tm = 0; tm < 2; ++tm) {
        #pragma unroll
        for (int tn = 0; tn < 4; ++tn) {
            int n = n0 + wn + tn * 8 + tig * 2;
            float b0v = bias0 ? bias0[n]     : 0.f;
            float b1v = bias0 ? bias0[n + 1] : 0.f;
            if (bias1) { b0v += bias1[n]; b1v += bias1[n + 1]; }
            int m = m0 + wm + tm * 16 + gid;
            float2 v0 = {acc[tm][tn][0] + b0v, acc[tm][tn][1] + b1v};
            float2 v1 = {acc[tm][tn][2] + b0v, acc[tm][tn][3] + b1v};
            *(float2*)(C + (size_t)m * N + n)       = v0;
            *(float2*)(C + (size_t)(m + 8) * N + n) = v1;
        }
    }
}

// ----------------------------------------------------------------------------
// LSTM elementwise: gates (i,f,g,o) -> hy
// ----------------------------------------------------------------------------
__global__ __launch_bounds__(256) void lstm_elem_kernel(
    const float* __restrict__ cx, float* __restrict__ hy)
{
    int idx = blockIdx.x * blockDim.x + threadIdx.x;
    int b = idx >> 9, h = idx & 511;
    const float* g = g_gates + (size_t)b * 2048;
    float gi = g[h];
    float gf = g[512 + h];
    float gg = g[1024 + h];
    float go = g[1536 + h];
    float cn = sigm(gf) * cx[idx] + sigm(gi) * tanhapx(gg);
    hy[idx] = sigm(go) * tanhapx(cn);
}

// ----------------------------------------------------------------------------
// Fused attention: one CTA per batch row, 1024 threads.
// Streams features[b] (128 KB) from GMEM once: z computed on the fly while
// staging into pad-65 SMEM; softmax over K=64 (attn_b cancels); cy from SMEM.
// ----------------------------------------------------------------------------
__global__ __launch_bounds__(1024) void attn_kernel(
    const float* __restrict__ features,
    const float* __restrict__ attn_w,
    float* __restrict__ cy)
{
    extern __shared__ float sm[];
    float* SF  = sm;               // 512*65
    float* WhS = SF + 512 * 65;    // 512
    float* AW  = WhS + 512;        // 512
    float* ZP  = AW + 512;         // 1024 (16 x 64 partials; reused in phase 3)
    float* WK  = ZP + 1024;        // 64
    float* RED = WK + 64;          // 4

    const int b = blockIdx.x;
    const int tid = threadIdx.x;

    if (tid < 512) {
        WhS[tid] = g_wh[(size_t)b * 512 + tid];
        AW[tid]  = attn_w[tid];
    }
    __syncthreads();

    const int k = tid & 63;
    const int j = tid >> 6;   // 0..15: d-chunk of 32
    const float* fb = features + (size_t)b * (512 * 64);

    // Phase 1: stream + stage + partial z
    float zacc = 0.f;
    #pragma unroll 8
    for (int dd = 0; dd < 32; ++dd) {
        int d = j * 32 + dd;
        float v = fb[d * 64 + k];
        SF[d * 65 + k] = v;
        zacc = fmaf(tanhapx(v + WhS[d]), AW[d], zacc);
    }
    ZP[j * 64 + k] = zacc;
    __syncthreads();

    // Phase 2: reduce partials, softmax over K=64 (threads 0..63)
    float z = 0.f;
    if (tid < 64) {
        #pragma unroll
        for (int jj = 0; jj < 16; jj++) z += ZP[jj * 64 + tid];
    }
    float mv = (tid < 64) ? z : -CUDART_INF_F;
    #pragma unroll
    for (int off = 16; off; off >>= 1)
        mv = fmaxf(mv, __shfl_xor_sync(0xffffffffu, mv, off));
    if (tid < 64 && (tid & 31) == 0) RED[tid >> 5] = mv;
    __syncthreads();
    float mx = fmaxf(RED[0], RED[1]);
    float e = (tid < 64) ? __expf(z - mx) : 0.f;
    float sv = e;
    #pragma unroll
    for (int off = 16; off; off >>= 1)
        sv += __shfl_xor_sync(0xffffffffu, sv, off);
    if (tid < 64 && (tid & 31) == 0) RED[2 + (tid >> 5)] = sv;
    __syncthreads();
    float inv = 1.f / (RED[2] + RED[3]);
    if (tid < 64) WK[tid] = e * inv;
    __syncthreads();

    // Phase 3: cy[b,d] = sum_k SF[d,k]*w[k]; two threads per d (k halves)
    {
        const int d = tid & 511;
        const int half = tid >> 9;
        float acc = 0.f;
        #pragma unroll
        for (int kk = 0; kk < 32; ++kk)
            acc = fmaf(SF[d * 65 + half * 32 + kk], WK[half * 32 + kk], acc);
        ZP[half * 512 + d] = acc;   // reuse ZP
    }
    __syncthreads();
    if (tid < 512)
        cy[(size_t)b * 512 + tid] = ZP[tid] + ZP[512 + tid];
}

// ----------------------------------------------------------------------------
extern "C" void kernel_launch(void* const* d_in, const int* in_sizes, int n_in,
                              void* d_out, int out_size)
{
    const float* x      = (const float*)d_in[0];
    const float* hx     = (const float*)d_in[1];
    const float* cx     = (const float*)d_in[2];
    const float* feats  = (const float*)d_in[3];
    const float* W_ih   = (const float*)d_in[4];
    const float* W_hh   = (const float*)d_in[5];
    const float* b_ih   = (const float*)d_in[6];
    const float* b_hh   = (const float*)d_in[7];
    const float* W_ht   = (const float*)d_in[8];
    const float* b_ht   = (const float*)d_in[9];
    const float* attn_w = (const float*)d_in[10];
    // attn_b (d_in[11]) cancels in softmax -> unused.

    float* hy = (float*)d_out;
    float* cy = (float*)d_out + Bdim * Hdim;

    float* gates; cudaGetSymbolAddress((void**)&gates, g_gates);
    float* wh;    cudaGetSymbolAddress((void**)&wh, g_wh);

    const int attn_smem = (512 * 65 + 512 + 512 + 1024 + 64 + 4) * (int)sizeof(float);
    cudaFuncSetAttribute(attn_kernel, cudaFuncAttributeMaxDynamicSharedMemorySize, attn_smem);

    // 1) gates = [x|hx] @ [W_ih|W_hh]^T + b_ih + b_hh  (K=1024 -> 64 tiles)
    gemm_tc_kernel<<<dim3(2048 / 64, 2048 / 128), 256>>>(
        x, hx, W_ih, W_hh, b_ih, b_hh, gates, 2048, 64);

    // 2) LSTM elementwise -> hy
    lstm_elem_kernel<<<(Bdim * Hdim) / 256, 256>>>(cx, hy);

    // 3) Wh = hy @ W_ht^T + b_ht  (K=512 -> 32 tiles)
    gemm_tc_kernel<<<dim3(512 / 64, 2048 / 128), 256>>>(
        hy, hy, W_ht, W_ht, b_ht, nullptr, wh, 512, 32);

    // 4) fused attention -> cy
    attn_kernel<<<Bdim, 1024, attn_smem>>>(feats, attn_w, cy);
}

// round 5
// speedup vs baseline: 2.0546x; 1.0580x over previous
#include <cuda_runtime.h>
#include <cuda_bf16.h>
#include <math_constants.h>
#include <stdint.h>

// ----------------------------------------------------------------------------
// LSTMSpatial: B=2048, E=H=D=512, K=64
// ----------------------------------------------------------------------------

#define Bdim 2048
#define Hdim 512

// Scratch (device globals: allocation-free rule)
__device__ float g_gates[Bdim * 4 * Hdim];                 // 16 MB
__device__ float g_wh[Bdim * Hdim];                        //  4 MB
__device__ __nv_bfloat16 g_abf[Bdim * 1024];               // [x|hx] hi
__device__ __nv_bfloat16 g_alf[Bdim * 1024];               // [x|hx] lo
__device__ __nv_bfloat16 g_wbf[2048 * 1024];               // [W_ih|W_hh] hi
__device__ __nv_bfloat16 g_wlf[2048 * 1024];               // lo
__device__ __nv_bfloat16 g_wtbf[512 * 512];                // W_ht hi
__device__ __nv_bfloat16 g_wtlf[512 * 512];                // W_ht lo
__device__ __nv_bfloat16 g_hybf[Bdim * 512];               // hy hi
__device__ __nv_bfloat16 g_hylf[Bdim * 512];               // hy lo

__device__ __forceinline__ float tanhapx(float x) {
    float y;
    asm("tanh.approx.f32 %0, %1;" : "=f"(y) : "f"(x));
    return y;
}
__device__ __forceinline__ float sigm(float x) {
    return fmaf(0.5f, tanhapx(0.5f * x), 0.5f);
}

__device__ __forceinline__ void cp16(uint32_t smem_dst, const void* gsrc) {
    asm volatile("cp.async.cg.shared.global [%0], [%1], 16;"
                 :: "r"(smem_dst), "l"(gsrc));
}
#define CP_COMMIT() asm volatile("cp.async.commit_group;")

// ----------------------------------------------------------------------------
// Conversion kernels: f32 -> (hi, lo) bf16
// ----------------------------------------------------------------------------
__device__ __forceinline__ void split_f4(
    float4 v, __nv_bfloat16* hi, __nv_bfloat16* lo, size_t off)
{
    float2 p0 = {v.x, v.y}, p1 = {v.z, v.w};
    __nv_bfloat162 h0 = __float22bfloat162_rn(p0);
    __nv_bfloat162 h1 = __float22bfloat162_rn(p1);
    float2 r0 = {p0.x - __bfloat162float(h0.x), p0.y - __bfloat162float(h0.y)};
    float2 r1 = {p1.x - __bfloat162float(h1.x), p1.y - __bfloat162float(h1.y)};
    *(__nv_bfloat162*)(hi + off)     = h0;
    *(__nv_bfloat162*)(hi + off + 2) = h1;
    *(__nv_bfloat162*)(lo + off)     = __float22bfloat162_rn(r0);
    *(__nv_bfloat162*)(lo + off + 2) = __float22bfloat162_rn(r1);
}

// concat two [rows][512] f32 sources into [rows][1024] hi/lo bf16
__global__ __launch_bounds__(256) void convert_cat_kernel(
    const float* __restrict__ s0, const float* __restrict__ s1,
    __nv_bfloat16* __restrict__ hi, __nv_bfloat16* __restrict__ lo, int nf4)
{
    int e = blockIdx.x * blockDim.x + threadIdx.x;
    if (e >= nf4) return;
    int row = e >> 8;            // 256 float4 per 1024-col row
    int col = (e & 255) * 4;
    const float* s = (col < 512) ? (s0 + (size_t)row * 512 + col)
                                 : (s1 + (size_t)row * 512 + col - 512);
    float4 v = *(const float4*)s;
    split_f4(v, hi, lo, (size_t)row * 1024 + col);
}

// flat single-source f32 -> hi/lo bf16
__global__ __launch_bounds__(256) void convert_single_kernel(
    const float* __restrict__ s,
    __nv_bfloat16* __restrict__ hi, __nv_bfloat16* __restrict__ lo, int nf4)
{
    int e = blockIdx.x * blockDim.x + threadIdx.x;
    if (e >= nf4) return;
    float4 v = *(const float4*)(s + (size_t)e * 4);
    split_f4(v, hi, lo, (size_t)e * 4);
}

// ----------------------------------------------------------------------------
// Tensor-core GEMM on pre-split bf16: C = Ah*Wh^T + Ah*Wl^T + Al*Wh^T + bias
// BM=128, BN=128, BK=32. 256 threads = 8 warps (4m x 2n), warp tile 32x64.
// cp.async double-buffered. smem rows padded to 40 bf16 (80B).
// ----------------------------------------------------------------------------
#define LDT 40
#define TILE_E (128 * LDT)          // 5120 bf16 per array
#define STAGE_E (4 * TILE_E)        // Ah, Al, Bh, Bl

#define MMA_BF16(acc, af, bf)                                                 \
    asm volatile("mma.sync.aligned.m16n8k16.row.col.f32.bf16.bf16.f32 "       \
                 "{%0,%1,%2,%3}, {%4,%5,%6,%7}, {%8,%9}, {%0,%1,%2,%3};"      \
                 : "+f"(acc[0]), "+f"(acc[1]), "+f"(acc[2]), "+f"(acc[3])     \
                 : "r"(af[0]), "r"(af[1]), "r"(af[2]), "r"(af[3]),            \
                   "r"(bf[0]), "r"(bf[1]))

#define LDSM4(r, addr)                                                        \
    asm volatile("ldmatrix.sync.aligned.m8n8.x4.shared.b16 {%0,%1,%2,%3}, [%4];" \
                 : "=r"(r[0]), "=r"(r[1]), "=r"(r[2]), "=r"(r[3]) : "r"(addr))

__global__ __launch_bounds__(256) void gemm_bf16_kernel(
    const __nv_bfloat16* __restrict__ Ahg, const __nv_bfloat16* __restrict__ Alg,
    const __nv_bfloat16* __restrict__ Whg, const __nv_bfloat16* __restrict__ Wlg,
    const float* __restrict__ bias0, const float* __restrict__ bias1,
    float* __restrict__ C, int N, int Kb)
{
    extern __shared__ __nv_bfloat16 gsm[];
    const int nkt = Kb >> 5;
    const int tid = threadIdx.x;
    const int wid = tid >> 5, lane = tid & 31;
    const int m0 = blockIdx.y * 128, n0 = blockIdx.x * 128;
    const int wm = (wid & 3) * 32;
    const int wn = (wid >> 2) * 64;

    // ldmatrix lane addressing
    const int rowA = lane & 15, chA = lane >> 4;
    const int q = lane >> 3, rB = lane & 7;
    const int rowB = rB + ((q >> 1) << 3), chB = q & 1;

    float acc[2][8][4];
    #pragma unroll
    for (int i = 0; i < 2; i++)
        #pragma unroll
        for (int j = 0; j < 8; j++)
            #pragma unroll
            for (int r = 0; r < 4; r++) acc[i][j][r] = 0.f;

    const uint32_t smem_base = (uint32_t)__cvta_generic_to_shared(gsm);

    // stage loader: 8 x 16B cp.async per thread
    auto load_stage = [&](int s, int kt) {
        const int k0 = kt * 32;
        uint32_t sb = smem_base + (uint32_t)(s * STAGE_E) * 2;
        #pragma unroll
        for (int h = 0; h < 2; ++h) {
            int chunk = tid + h * 256;          // 0..511
            int row = chunk >> 2, c = chunk & 3;
            uint32_t doff = (uint32_t)(row * LDT + c * 8) * 2;
            size_t aof = (size_t)(m0 + row) * Kb + k0 + c * 8;
            size_t bof = (size_t)(n0 + row) * Kb + k0 + c * 8;
            cp16(sb + 0 * TILE_E * 2 + doff, Ahg + aof);
            cp16(sb + 1 * TILE_E * 2 + doff, Alg + aof);
            cp16(sb + 2 * TILE_E * 2 + doff, Whg + bof);
            cp16(sb + 3 * TILE_E * 2 + doff, Wlg + bof);
        }
        CP_COMMIT();
    };

    load_stage(0, 0);

    for (int kt = 0; kt < nkt; ++kt) {
        if (kt + 1 < nkt) {
            load_stage((kt + 1) & 1, kt + 1);
            asm volatile("cp.async.wait_group 1;");
        } else {
            asm volatile("cp.async.wait_group 0;");
        }
        __syncthreads();

        const int s = kt & 1;
        uint32_t ah_s = smem_base + (uint32_t)(s * STAGE_E + 0 * TILE_E) * 2;
        uint32_t al_s = smem_base + (uint32_t)(s * STAGE_E + 1 * TILE_E) * 2;
        uint32_t bh_s = smem_base + (uint32_t)(s * STAGE_E + 2 * TILE_E) * 2;
        uint32_t bl_s = smem_base + (uint32_t)(s * STAGE_E + 3 * TILE_E) * 2;

        #pragma unroll
        for (int ks = 0; ks < 2; ++ks) {
            const int kb = ks * 16;
            uint32_t ahf[2][4], alf[2][4], bhf[8][2], blf[8][2];
            #pragma unroll
            for (int tm = 0; tm < 2; ++tm) {
                uint32_t off = (uint32_t)((wm + tm * 16 + rowA) * LDT + kb + chA * 8) * 2;
                LDSM4(ahf[tm], ah_s + off);
                LDSM4(alf[tm], al_s + off);
            }
            #pragma unroll
            for (int p = 0; p < 4; ++p) {
                uint32_t r4[4];
                uint32_t off = (uint32_t)((wn + p * 16 + rowB) * LDT + kb + chB * 8) * 2;
                LDSM4(r4, bh_s + off);
                bhf[2*p][0] = r4[0]; bhf[2*p][1] = r4[1];
                bhf[2*p+1][0] = r4[2]; bhf[2*p+1][1] = r4[3];
                LDSM4(r4, bl_s + off);
                blf[2*p][0] = r4[0]; blf[2*p][1] = r4[1];
                blf[2*p+1][0] = r4[2]; blf[2*p+1][1] = r4[3];
            }
            #pragma unroll
            for (int tm = 0; tm < 2; ++tm)
                #pragma unroll
                for (int tn = 0; tn < 8; ++tn) {
                    MMA_BF16(acc[tm][tn], ahf[tm], bhf[tn]);
                    MMA_BF16(acc[tm][tn], ahf[tm], blf[tn]);
                    MMA_BF16(acc[tm][tn], alf[tm], bhf[tn]);
                }
        }
        __syncthreads();
    }

    // epilogue
    const int gid = lane >> 2, tig = lane & 3;
    #pragma unroll
    for (int tm = 0; tm < 2; ++tm) {
        #pragma unroll
        for (int tn = 0; tn < 8; ++tn) {
            int n = n0 + wn + tn * 8 + tig * 2;
            float b0v = bias0 ? bias0[n]     : 0.f;
            float b1v = bias0 ? bias0[n + 1] : 0.f;
            if (bias1) { b0v += bias1[n]; b1v += bias1[n + 1]; }
            int m = m0 + wm + tm * 16 + gid;
            float2 v0 = {acc[tm][tn][0] + b0v, acc[tm][tn][1] + b1v};
            float2 v1 = {acc[tm][tn][2] + b0v, acc[tm][tn][3] + b1v};
            *(float2*)(C + (size_t)m * N + n)       = v0;
            *(float2*)(C + (size_t)(m + 8) * N + n) = v1;
        }
    }
}

// ----------------------------------------------------------------------------
// LSTM elementwise: gates -> hy (f32) + hy hi/lo bf16 for GEMM2
// ----------------------------------------------------------------------------
__global__ __launch_bounds__(256) void lstm_elem_kernel(
    const float* __restrict__ cx, float* __restrict__ hy)
{
    int idx = blockIdx.x * blockDim.x + threadIdx.x;
    int b = idx >> 9, h = idx & 511;
    const float* g = g_gates + (size_t)b * 2048;
    float gi = g[h];
    float gf = g[512 + h];
    float gg = g[1024 + h];
    float go = g[1536 + h];
    float cn = sigm(gf) * cx[idx] + sigm(gi) * tanhapx(gg);
    float v = sigm(go) * tanhapx(cn);
    hy[idx] = v;
    __nv_bfloat16 hb = __float2bfloat16(v);
    g_hybf[idx] = hb;
    g_hylf[idx] = __float2bfloat16(v - __bfloat162float(hb));
}

// ----------------------------------------------------------------------------
// Fused attention: one CTA per batch row, 1024 threads, cp.async staging.
// SF rows padded to 68 floats (272B, 16B aligned).
// ----------------------------------------------------------------------------
__global__ __launch_bounds__(1024) void attn_kernel(
    const float* __restrict__ features,
    const float* __restrict__ attn_w,
    float* __restrict__ cy)
{
    extern __shared__ float sm[];
    float* SF  = sm;               // 512*68
    float* WhS = SF + 512 * 68;    // 512
    float* AW  = WhS + 512;        // 512
    float* ZP  = AW + 512;         // 1024
    float* WK  = ZP + 1024;        // 64  (16B aligned)
    float* RED = WK + 64;          // 4

    const int b = blockIdx.x;
    const int tid = threadIdx.x;
    const float* fb = features + (size_t)b * (512 * 64);

    const uint32_t sf_s = (uint32_t)__cvta_generic_to_shared(SF);
    const int dloc = tid >> 4, seg = tid & 15;

    // issue 8 chunk copies (64 d-rows / 16KB each), committed per chunk
    #pragma unroll
    for (int c = 0; c < 8; ++c) {
        uint32_t dst = sf_s + (uint32_t)((c * 64 + dloc) * 68 + seg * 4) * 4;
        cp16(dst, fb + c * 4096 + tid * 4);
        CP_COMMIT();
    }

    if (tid < 512) {
        WhS[tid] = g_wh[(size_t)b * 512 + tid];
        AW[tid]  = attn_w[tid];
    }

    const int k = tid & 63;
    const int j = tid >> 6;   // 0..15
    float zacc = 0.f;

    // Phase 1: per-chunk z compute, trailing the async copies
#define ATTN_CHUNK(c, WAITN)                                                  \
    {                                                                         \
        asm volatile("cp.async.wait_group %0;" :: "n"(WAITN));                \
        __syncthreads();                                                      \
        _Pragma("unroll")                                                     \
        for (int dd = 0; dd < 4; ++dd) {                                      \
            int d = (c) * 64 + j * 4 + dd;                                    \
            float v = SF[d * 68 + k];                                         \
            zacc = fmaf(tanhapx(v + WhS[d]), AW[d], zacc);                    \
        }                                                                     \
    }
    ATTN_CHUNK(0, 7) ATTN_CHUNK(1, 6) ATTN_CHUNK(2, 5) ATTN_CHUNK(3, 4)
    ATTN_CHUNK(4, 3) ATTN_CHUNK(5, 2) ATTN_CHUNK(6, 1) ATTN_CHUNK(7, 0)
#undef ATTN_CHUNK

    ZP[j * 64 + k] = zacc;
    __syncthreads();

    // Phase 2: softmax over K=64 (threads 0..63); attn_b cancels
    float z = 0.f;
    if (tid < 64) {
        #pragma unroll
        for (int jj = 0; jj < 16; jj++) z += ZP[jj * 64 + tid];
    }
    float mv = (tid < 64) ? z : -CUDART_INF_F;
    #pragma unroll
    for (int off = 16; off; off >>= 1)
        mv = fmaxf(mv, __shfl_xor_sync(0xffffffffu, mv, off));
    if (tid < 64 && (tid & 31) == 0) RED[tid >> 5] = mv;
    __syncthreads();
    float mx = fmaxf(RED[0], RED[1]);
    float e = (tid < 64) ? __expf(z - mx) : 0.f;
    float sv = e;
    #pragma unroll
    for (int off = 16; off; off >>= 1)
        sv += __shfl_xor_sync(0xffffffffu, sv, off);
    if (tid < 64 && (tid & 31) == 0) RED[2 + (tid >> 5)] = sv;
    __syncthreads();
    float inv = 1.f / (RED[2] + RED[3]);
    if (tid < 64) WK[tid] = e * inv;
    __syncthreads();

    // Phase 3: cy[b,d] = sum_k SF[d,k]*w[k]; 2 threads per d, float4 LDS
    {
        const int d = tid & 511;
        const int half = tid >> 9;
        const float* sfr = SF + d * 68 + half * 32;
        const float* wkr = WK + half * 32;
        float a = 0.f;
        #pragma unroll
        for (int kk = 0; kk < 8; ++kk) {
            float4 f = *(const float4*)(sfr + kk * 4);
            float4 w = *(const float4*)(wkr + kk * 4);
            a = fmaf(f.x, w.x, a); a = fmaf(f.y, w.y, a);
            a = fmaf(f.z, w.z, a); a = fmaf(f.w, w.w, a);
        }
        ZP[half * 512 + d] = a;
    }
    __syncthreads();
    if (tid < 512)
        cy[(size_t)b * 512 + tid] = ZP[tid] + ZP[512 + tid];
}

// ----------------------------------------------------------------------------
extern "C" void kernel_launch(void* const* d_in, const int* in_sizes, int n_in,
                              void* d_out, int out_size)
{
    const float* x      = (const float*)d_in[0];
    const float* hx     = (const float*)d_in[1];
    const float* cx     = (const float*)d_in[2];
    const float* feats  = (const float*)d_in[3];
    const float* W_ih   = (const float*)d_in[4];
    const float* W_hh   = (const float*)d_in[5];
    const float* b_ih   = (const float*)d_in[6];
    const float* b_hh   = (const float*)d_in[7];
    const float* W_ht   = (const float*)d_in[8];
    const float* b_ht   = (const float*)d_in[9];
    const float* attn_w = (const float*)d_in[10];
    // attn_b (d_in[11]) cancels in softmax -> unused.

    float* hy = (float*)d_out;
    float* cy = (float*)d_out + Bdim * Hdim;

    float* gates; cudaGetSymbolAddress((void**)&gates, g_gates);
    float* wh;    cudaGetSymbolAddress((void**)&wh, g_wh);
    __nv_bfloat16 *abf, *alf, *wbf, *wlf, *wtbf, *wtlf, *hybf, *hylf;
    cudaGetSymbolAddress((void**)&abf,  g_abf);
    cudaGetSymbolAddress((void**)&alf,  g_alf);
    cudaGetSymbolAddress((void**)&wbf,  g_wbf);
    cudaGetSymbolAddress((void**)&wlf,  g_wlf);
    cudaGetSymbolAddress((void**)&wtbf, g_wtbf);
    cudaGetSymbolAddress((void**)&wtlf, g_wtlf);
    cudaGetSymbolAddress((void**)&hybf, g_hybf);
    cudaGetSymbolAddress((void**)&hylf, g_hylf);

    const int gemm_smem = 2 * STAGE_E * (int)sizeof(__nv_bfloat16);  // 81920
    cudaFuncSetAttribute(gemm_bf16_kernel,
                         cudaFuncAttributeMaxDynamicSharedMemorySize, gemm_smem);
    const int attn_smem = (512 * 68 + 512 + 512 + 1024 + 64 + 4) * (int)sizeof(float);
    cudaFuncSetAttribute(attn_kernel,
                         cudaFuncAttributeMaxDynamicSharedMemorySize, attn_smem);

    // 0) precompute bf16 hi/lo splits
    convert_cat_kernel<<<(2048 * 256) / 256, 256>>>(x, hx, abf, alf, 2048 * 256);
    convert_cat_kernel<<<(2048 * 256) / 256, 256>>>(W_ih, W_hh, wbf, wlf, 2048 * 256);
    convert_single_kernel<<<(512 * 128) / 256, 256>>>(W_ht, wtbf, wtlf, 512 * 128);

    // 1) gates = [x|hx] @ [W_ih|W_hh]^T + b_ih + b_hh  (Kb=1024)
    gemm_bf16_kernel<<<dim3(2048 / 128, 2048 / 128), 256, gemm_smem>>>(
        abf, alf, wbf, wlf, b_ih, b_hh, gates, 2048, 1024);

    // 2) LSTM elementwise -> hy (+ bf16 split)
    lstm_elem_kernel<<<(Bdim * Hdim) / 256, 256>>>(cx, hy);

    // 3) Wh = hy @ W_ht^T + b_ht  (Kb=512)
    gemm_bf16_kernel<<<dim3(512 / 128, 2048 / 128), 256, gemm_smem>>>(
        hybf, hylf, wtbf, wtlf, b_ht, nullptr, wh, 512, 512);

    // 4) fused attention -> cy
    attn_kernel<<<Bdim, 1024, attn_smem>>>(feats, attn_w, cy);
}

// round 8
// speedup vs baseline: 2.5323x; 1.2325x over previous
#include <cuda_runtime.h>
#include <cuda_bf16.h>
#include <math_constants.h>
#include <stdint.h>

// ----------------------------------------------------------------------------
// LSTMSpatial: B=2048, E=H=D=512, K=64   (sm_103 legacy-HMMA path; tcgen05
// rejected by this harness's compute_103 ptx target)
// ----------------------------------------------------------------------------

#define Bdim 2048
#define Hdim 512

// Scratch (device globals: allocation-free rule)
__device__ float g_gates[Bdim * 4 * Hdim];                 // 16 MB
__device__ float g_wh[Bdim * Hdim];                        //  4 MB (split-K part 0)
__device__ float g_wh2[Bdim * Hdim];                       //  4 MB (split-K part 1)
__device__ __nv_bfloat16 g_abf[Bdim * 1024];               // [x|hx] hi
__device__ __nv_bfloat16 g_alf[Bdim * 1024];               // [x|hx] lo
__device__ __nv_bfloat16 g_wbf[2048 * 1024];               // [W_ih|W_hh] hi
__device__ __nv_bfloat16 g_wlf[2048 * 1024];               // lo
__device__ __nv_bfloat16 g_wtbf[512 * 512];                // W_ht hi
__device__ __nv_bfloat16 g_wtlf[512 * 512];                // W_ht lo
__device__ __nv_bfloat16 g_hybf[Bdim * 512];               // hy hi
__device__ __nv_bfloat16 g_hylf[Bdim * 512];               // hy lo

__device__ __forceinline__ float tanhapx(float x) {
    float y;
    asm("tanh.approx.f32 %0, %1;" : "=f"(y) : "f"(x));
    return y;
}
__device__ __forceinline__ float sigm(float x) {
    return fmaf(0.5f, tanhapx(0.5f * x), 0.5f);
}

__device__ __forceinline__ void cp16(uint32_t smem_dst, const void* gsrc) {
    asm volatile("cp.async.cg.shared.global [%0], [%1], 16;"
                 :: "r"(smem_dst), "l"(gsrc));
}
#define CP_COMMIT() asm volatile("cp.async.commit_group;")

// ----------------------------------------------------------------------------
// Merged conversion kernel: f32 -> (hi, lo) bf16 for all three operands
// ----------------------------------------------------------------------------
__device__ __forceinline__ void split_f4(
    float4 v, __nv_bfloat16* hi, __nv_bfloat16* lo, size_t off)
{
    float2 p0 = {v.x, v.y}, p1 = {v.z, v.w};
    __nv_bfloat162 h0 = __float22bfloat162_rn(p0);
    __nv_bfloat162 h1 = __float22bfloat162_rn(p1);
    float2 r0 = {p0.x - __bfloat162float(h0.x), p0.y - __bfloat162float(h0.y)};
    float2 r1 = {p1.x - __bfloat162float(h1.x), p1.y - __bfloat162float(h1.y)};
    *(__nv_bfloat162*)(hi + off)     = h0;
    *(__nv_bfloat162*)(hi + off + 2) = h1;
    *(__nv_bfloat162*)(lo + off)     = __float22bfloat162_rn(r0);
    *(__nv_bfloat162*)(lo + off + 2) = __float22bfloat162_rn(r1);
}

#define N0CAT (2048 * 256)
#define N1CAT (2048 * 256)
#define N2SGL (512 * 128)

__global__ __launch_bounds__(256) void convert_all_kernel(
    const float* __restrict__ x,    const float* __restrict__ hx,
    const float* __restrict__ Wih,  const float* __restrict__ Whh,
    const float* __restrict__ Wht)
{
    int e = blockIdx.x * blockDim.x + threadIdx.x;
    if (e < N0CAT) {
        int row = e >> 8, col = (e & 255) * 4;
        const float* s = (col < 512) ? (x + (size_t)row * 512 + col)
                                     : (hx + (size_t)row * 512 + col - 512);
        split_f4(*(const float4*)s, g_abf, g_alf, (size_t)row * 1024 + col);
    } else if (e < N0CAT + N1CAT) {
        int e2 = e - N0CAT;
        int row = e2 >> 8, col = (e2 & 255) * 4;
        const float* s = (col < 512) ? (Wih + (size_t)row * 512 + col)
                                     : (Whh + (size_t)row * 512 + col - 512);
        split_f4(*(const float4*)s, g_wbf, g_wlf, (size_t)row * 1024 + col);
    } else {
        int e2 = e - N0CAT - N1CAT;
        if (e2 < N2SGL)
            split_f4(*(const float4*)(Wht + (size_t)e2 * 4),
                     g_wtbf, g_wtlf, (size_t)e2 * 4);
    }
}

// ----------------------------------------------------------------------------
// Tensor-core GEMM on pre-split bf16: C = Ah*Wh^T + Ah*Wl^T + Al*Wh^T + bias
// BM=128, BN=128, BK=32. 256 threads = 8 warps (4m x 2n), warp tile 32x64.
// cp.async double-buffered. Term-outer MMA order: 16 independent accs between
// same-acc reuses (kills acc RAW stalls). gridDim.z = split-K parts.
// ----------------------------------------------------------------------------
#define LDT 40
#define TILE_E (128 * LDT)
#define STAGE_E (4 * TILE_E)

#define MMA_BF16(acc, af, bf)                                                 \
    asm volatile("mma.sync.aligned.m16n8k16.row.col.f32.bf16.bf16.f32 "       \
                 "{%0,%1,%2,%3}, {%4,%5,%6,%7}, {%8,%9}, {%0,%1,%2,%3};"      \
                 : "+f"(acc[0]), "+f"(acc[1]), "+f"(acc[2]), "+f"(acc[3])     \
                 : "r"(af[0]), "r"(af[1]), "r"(af[2]), "r"(af[3]),            \
                   "r"(bf[0]), "r"(bf[1]))

#define LDSM4(r, addr)                                                        \
    asm volatile("ldmatrix.sync.aligned.m8n8.x4.shared.b16 {%0,%1,%2,%3}, [%4];" \
                 : "=r"(r[0]), "=r"(r[1]), "=r"(r[2]), "=r"(r[3]) : "r"(addr))

__global__ __launch_bounds__(256) void gemm_bf16_kernel(
    const __nv_bfloat16* __restrict__ Ahg, const __nv_bfloat16* __restrict__ Alg,
    const __nv_bfloat16* __restrict__ Whg, const __nv_bfloat16* __restrict__ Wlg,
    const float* __restrict__ bias0, const float* __restrict__ bias1,
    float* __restrict__ C0, float* __restrict__ C1,
    int N, int Kstride, int Kslice)
{
    extern __shared__ __nv_bfloat16 gsm[];
    const int nkt = Kslice >> 5;
    const int koff = blockIdx.z * Kslice;
    const int tid = threadIdx.x;
    const int wid = tid >> 5, lane = tid & 31;
    const int m0 = blockIdx.y * 128, n0 = blockIdx.x * 128;
    const int wm = (wid & 3) * 32;
    const int wn = (wid >> 2) * 64;

    float* C = C0;
    const float* bb0 = bias0;
    const float* bb1 = bias1;
    if (blockIdx.z) { C = C1; bb0 = nullptr; bb1 = nullptr; }

    const int rowA = lane & 15, chA = lane >> 4;
    const int q = lane >> 3, rB = lane & 7;
    const int rowB = rB + ((q >> 1) << 3), chB = q & 1;

    float acc[2][8][4];
    #pragma unroll
    for (int i = 0; i < 2; i++)
        #pragma unroll
        for (int j = 0; j < 8; j++)
            #pragma unroll
            for (int r = 0; r < 4; r++) acc[i][j][r] = 0.f;

    const uint32_t smem_base = (uint32_t)__cvta_generic_to_shared(gsm);

    auto load_stage = [&](int s, int kt) {
        const int k0 = koff + kt * 32;
        uint32_t sb = smem_base + (uint32_t)(s * STAGE_E) * 2;
        #pragma unroll
        for (int h = 0; h < 2; ++h) {
            int chunk = tid + h * 256;
            int row = chunk >> 2, c = chunk & 3;
            uint32_t doff = (uint32_t)(row * LDT + c * 8) * 2;
            size_t aof = (size_t)(m0 + row) * Kstride + k0 + c * 8;
            size_t bof = (size_t)(n0 + row) * Kstride + k0 + c * 8;
            cp16(sb + 0 * TILE_E * 2 + doff, Ahg + aof);
            cp16(sb + 1 * TILE_E * 2 + doff, Alg + aof);
            cp16(sb + 2 * TILE_E * 2 + doff, Whg + bof);
            cp16(sb + 3 * TILE_E * 2 + doff, Wlg + bof);
        }
        CP_COMMIT();
    };

    load_stage(0, 0);

    for (int kt = 0; kt < nkt; ++kt) {
        if (kt + 1 < nkt) {
            load_stage((kt + 1) & 1, kt + 1);
            asm volatile("cp.async.wait_group 1;");
        } else {
            asm volatile("cp.async.wait_group 0;");
        }
        __syncthreads();

        const int s = kt & 1;
        uint32_t ah_s = smem_base + (uint32_t)(s * STAGE_E + 0 * TILE_E) * 2;
        uint32_t al_s = smem_base + (uint32_t)(s * STAGE_E + 1 * TILE_E) * 2;
        uint32_t bh_s = smem_base + (uint32_t)(s * STAGE_E + 2 * TILE_E) * 2;
        uint32_t bl_s = smem_base + (uint32_t)(s * STAGE_E + 3 * TILE_E) * 2;

        #pragma unroll
        for (int ks = 0; ks < 2; ++ks) {
            const int kb = ks * 16;
            uint32_t ahf[2][4], alf[2][4], bhf[8][2], blf[8][2];
            #pragma unroll
            for (int tm = 0; tm < 2; ++tm) {
                uint32_t off = (uint32_t)((wm + tm * 16 + rowA) * LDT + kb + chA * 8) * 2;
                LDSM4(ahf[tm], ah_s + off);
                LDSM4(alf[tm], al_s + off);
            }
            #pragma unroll
            for (int p = 0; p < 4; ++p) {
                uint32_t r4[4];
                uint32_t off = (uint32_t)((wn + p * 16 + rowB) * LDT + kb + chB * 8) * 2;
                LDSM4(r4, bh_s + off);
                bhf[2*p][0] = r4[0]; bhf[2*p][1] = r4[1];
                bhf[2*p+1][0] = r4[2]; bhf[2*p+1][1] = r4[3];
                LDSM4(r4, bl_s + off);
                blf[2*p][0] = r4[0]; blf[2*p][1] = r4[1];
                blf[2*p+1][0] = r4[2]; blf[2*p+1][1] = r4[3];
            }
            // term-outer order: consecutive MMAs hit different accumulators
            #pragma unroll
            for (int tm = 0; tm < 2; ++tm)
                #pragma unroll
                for (int tn = 0; tn < 8; ++tn)
                    MMA_BF16(acc[tm][tn], ahf[tm], bhf[tn]);
            #pragma unroll
            for (int tm = 0; tm < 2; ++tm)
                #pragma unroll
                for (int tn = 0; tn < 8; ++tn)
                    MMA_BF16(acc[tm][tn], ahf[tm], blf[tn]);
            #pragma unroll
            for (int tm = 0; tm < 2; ++tm)
                #pragma unroll
                for (int tn = 0; tn < 8; ++tn)
                    MMA_BF16(acc[tm][tn], alf[tm], bhf[tn]);
        }
        __syncthreads();
    }

    const int gid = lane >> 2, tig = lane & 3;
    #pragma unroll
    for (int tm = 0; tm < 2; ++tm) {
        #pragma unroll
        for (int tn = 0; tn < 8; ++tn) {
            int n = n0 + wn + tn * 8 + tig * 2;
            float b0v = bb0 ? bb0[n]     : 0.f;
            float b1v = bb0 ? bb0[n + 1] : 0.f;
            if (bb1) { b0v += bb1[n]; b1v += bb1[n + 1]; }
            int m = m0 + wm + tm * 16 + gid;
            float2 v0 = {acc[tm][tn][0] + b0v, acc[tm][tn][1] + b1v};
            float2 v1 = {acc[tm][tn][2] + b0v, acc[tm][tn][3] + b1v};
            *(float2*)(C + (size_t)m * N + n)       = v0;
            *(float2*)(C + (size_t)(m + 8) * N + n) = v1;
        }
    }
}

// ----------------------------------------------------------------------------
// LSTM elementwise: gates -> hy (f32) + hy hi/lo bf16 for GEMM2
// ----------------------------------------------------------------------------
__global__ __launch_bounds__(256) void lstm_elem_kernel(
    const float* __restrict__ cx, float* __restrict__ hy)
{
    int idx = blockIdx.x * blockDim.x + threadIdx.x;
    int b = idx >> 9, h = idx & 511;
    const float* g = g_gates + (size_t)b * 2048;
    float gi = g[h];
    float gf = g[512 + h];
    float gg = g[1024 + h];
    float go = g[1536 + h];
    float cn = sigm(gf) * cx[idx] + sigm(gi) * tanhapx(gg);
    float v = sigm(go) * tanhapx(cn);
    hy[idx] = v;
    __nv_bfloat16 hb = __float2bfloat16(v);
    g_hybf[idx] = hb;
    g_hylf[idx] = __float2bfloat16(v - __bfloat162float(hb));
}

// ----------------------------------------------------------------------------
// Cluster-2 fused attention: 2 CTAs per batch row, 512 threads each.
// Each CTA stages 256 d-rows (74 KB smem -> 3 CTAs/SM). Partial z exchanged
// via DSMEM (64 floats) + one cluster barrier; softmax duplicated; cy d-split.
// ----------------------------------------------------------------------------
__global__ __launch_bounds__(512) __cluster_dims__(2, 1, 1)
void attn_kernel(
    const float* __restrict__ features,
    const float* __restrict__ attn_w,
    float* __restrict__ cy)
{
    extern __shared__ float sm[];
    float* SF  = sm;               // 256*68
    float* WhS = SF + 256 * 68;    // 256
    float* AW  = WhS + 256;        // 256
    float* ZP  = AW + 256;         // 512
    float* WK  = ZP + 512;         // 64
    float* ZEX = WK + 64;          // 64 (peer's partial lands here)
    float* RED = ZEX + 64;         // 4

    const int b    = blockIdx.x >> 1;
    const int half = blockIdx.x & 1;   // == cluster rank
    const int tid  = threadIdx.x;
    const float* fb = features + (size_t)b * (512 * 64) + (size_t)half * 256 * 64;

    const uint32_t sf_s = (uint32_t)__cvta_generic_to_shared(SF);
    const int dloc = tid >> 4, seg = tid & 15;

    // 8 chunks x 32 rows (8KB each), one cp16 per thread per chunk
    #pragma unroll
    for (int c = 0; c < 8; ++c) {
        uint32_t dst = sf_s + (uint32_t)((c * 32 + dloc) * 68 + seg * 4) * 4;
        cp16(dst, fb + c * 2048 + tid * 4);
        CP_COMMIT();
    }

    if (tid < 256) {
        int dg = half * 256 + tid;
        WhS[tid] = g_wh[(size_t)b * 512 + dg] + g_wh2[(size_t)b * 512 + dg];
        AW[tid]  = attn_w[dg];
    }

    const int k = tid & 63;
    const int j = tid >> 6;   // 0..7
    float zacc = 0.f;

#define ATTN_CHUNK(c, WAITN)                                                  \
    {                                                                         \
        asm volatile("cp.async.wait_group %0;" :: "n"(WAITN));                \
        __syncthreads();                                                      \
        _Pragma("unroll")                                                     \
        for (int dd = 0; dd < 4; ++dd) {                                      \
            int d = (c) * 32 + j * 4 + dd;                                    \
            float v = SF[d * 68 + k];                                         \
            zacc = fmaf(tanhapx(v + WhS[d]), AW[d], zacc);                    \
        }                                                                     \
    }
    ATTN_CHUNK(0, 7) ATTN_CHUNK(1, 6) ATTN_CHUNK(2, 5) ATTN_CHUNK(3, 4)
    ATTN_CHUNK(4, 3) ATTN_CHUNK(5, 2) ATTN_CHUNK(6, 1) ATTN_CHUNK(7, 0)
#undef ATTN_CHUNK

    ZP[j * 64 + k] = zacc;
    __syncthreads();

    // local partial z_k (threads 0..63), then DSMEM exchange with peer CTA
    float zpart = 0.f;
    if (tid < 64) {
        #pragma unroll
        for (int jj = 0; jj < 8; jj++) zpart += ZP[jj * 64 + tid];
        uint32_t la = (uint32_t)__cvta_generic_to_shared(ZEX + tid);
        uint32_t ra;
        asm volatile("mapa.shared::cluster.u32 %0, %1, %2;"
                     : "=r"(ra) : "r"(la), "r"(half ^ 1));
        asm volatile("st.shared::cluster.f32 [%0], %1;"
                     :: "r"(ra), "f"(zpart) : "memory");
    }
    asm volatile("barrier.cluster.arrive.aligned;" ::: "memory");
    asm volatile("barrier.cluster.wait.aligned;" ::: "memory");

    // softmax over K=64 (threads 0..63, duplicated in both CTAs)
    float z = (tid < 64) ? (zpart + ZEX[tid]) : 0.f;
    float mv = (tid < 64) ? z : -CUDART_INF_F;
    #pragma unroll
    for (int off = 16; off; off >>= 1)
        mv = fmaxf(mv, __shfl_xor_sync(0xffffffffu, mv, off));
    if (tid < 64 && (tid & 31) == 0) RED[tid >> 5] = mv;
    __syncthreads();
    float mx = fmaxf(RED[0], RED[1]);
    float e = (tid < 64) ? __expf(z - mx) : 0.f;
    float sv = e;
    #pragma unroll
    for (int off = 16; off; off >>= 1)
        sv += __shfl_xor_sync(0xffffffffu, sv, off);
    if (tid < 64 && (tid & 31) == 0) RED[2 + (tid >> 5)] = sv;
    __syncthreads();
    float inv = 1.f / (RED[2] + RED[3]);
    if (tid < 64) WK[tid] = e * inv;
    __syncthreads();

    // cy for this CTA's 256 d-rows; 2 threads per d (k halves)
    {
        const int d = tid & 255;
        const int kh = tid >> 8;
        const float* sfr = SF + d * 68 + kh * 32;
        const float* wkr = WK + kh * 32;
        float a = 0.f;
        #pragma unroll
        for (int kk = 0; kk < 8; ++kk) {
            float4 f = *(const float4*)(sfr + kk * 4);
            float4 w = *(const float4*)(wkr + kk * 4);
            a = fmaf(f.x, w.x, a); a = fmaf(f.y, w.y, a);
            a = fmaf(f.z, w.z, a); a = fmaf(f.w, w.w, a);
        }
        ZP[kh * 256 + d] = a;
    }
    __syncthreads();
    if (tid < 256)
        cy[(size_t)b * 512 + half * 256 + tid] = ZP[tid] + ZP[256 + tid];
}

// ----------------------------------------------------------------------------
extern "C" void kernel_launch(void* const* d_in, const int* in_sizes, int n_in,
                              void* d_out, int out_size)
{
    const float* x      = (const float*)d_in[0];
    const float* hx     = (const float*)d_in[1];
    const float* cx     = (const float*)d_in[2];
    const float* feats  = (const float*)d_in[3];
    const float* W_ih   = (const float*)d_in[4];
    const float* W_hh   = (const float*)d_in[5];
    const float* b_ih   = (const float*)d_in[6];
    const float* b_hh   = (const float*)d_in[7];
    const float* W_ht   = (const float*)d_in[8];
    const float* b_ht   = (const float*)d_in[9];
    const float* attn_w = (const float*)d_in[10];
    // attn_b (d_in[11]) cancels in softmax -> unused.

    float* hy = (float*)d_out;
    float* cy = (float*)d_out + Bdim * Hdim;

    float* gates; cudaGetSymbolAddress((void**)&gates, g_gates);
    float* wh;    cudaGetSymbolAddress((void**)&wh,  g_wh);
    float* wh2;   cudaGetSymbolAddress((void**)&wh2, g_wh2);
    __nv_bfloat16 *abf, *alf, *wbf, *wlf, *wtbf, *wtlf, *hybf, *hylf;
    cudaGetSymbolAddress((void**)&abf,  g_abf);
    cudaGetSymbolAddress((void**)&alf,  g_alf);
    cudaGetSymbolAddress((void**)&wbf,  g_wbf);
    cudaGetSymbolAddress((void**)&wlf,  g_wlf);
    cudaGetSymbolAddress((void**)&wtbf, g_wtbf);
    cudaGetSymbolAddress((void**)&wtlf, g_wtlf);
    cudaGetSymbolAddress((void**)&hybf, g_hybf);
    cudaGetSymbolAddress((void**)&hylf, g_hylf);

    const int gemm_smem = 2 * STAGE_E * (int)sizeof(__nv_bfloat16);  // 81920
    cudaFuncSetAttribute(gemm_bf16_kernel,
                         cudaFuncAttributeMaxDynamicSharedMemorySize, gemm_smem);
    const int attn_smem = (256 * 68 + 256 + 256 + 512 + 64 + 64 + 4) * (int)sizeof(float);
    cudaFuncSetAttribute(attn_kernel,
                         cudaFuncAttributeMaxDynamicSharedMemorySize, attn_smem);

    // 0) all f32 -> hi/lo bf16 conversions in one launch
    const int ncv = N0CAT + N1CAT + N2SGL;
    convert_all_kernel<<<(ncv + 255) / 256, 256>>>(x, hx, W_ih, W_hh, W_ht);

    // 1) gates = [x|hx] @ [W_ih|W_hh]^T + b_ih + b_hh  (Kstride=Kslice=1024)
    gemm_bf16_kernel<<<dim3(16, 16, 1), 256, gemm_smem>>>(
        abf, alf, wbf, wlf, b_ih, b_hh, gates, nullptr, 2048, 1024, 1024);

    // 2) LSTM elementwise -> hy (+ bf16 split)
    lstm_elem_kernel<<<(Bdim * Hdim) / 256, 256>>>(cx, hy);

    // 3) Wh = hy @ W_ht^T + b_ht, split-K2 -> wh + wh2  (summed in attn)
    gemm_bf16_kernel<<<dim3(4, 16, 2), 256, gemm_smem>>>(
        hybf, hylf, wtbf, wtlf, b_ht, nullptr, wh, wh2, 512, 512, 256);

    // 4) cluster-2 fused attention -> cy
    attn_kernel<<<2 * Bdim, 512, attn_smem>>>(feats, attn_w, cy);
}